// round 1
// baseline (speedup 1.0000x reference)
#include <cuda_runtime.h>

#define NROWS 16384
#define NCOL  1024
#define G     16
#define NBLK  (NROWS / G)   /* 1024 blocks */
#define NTHR  256
#define NWARP (NTHR / 32)
#define NIT   20
#define CSS   64            /* colsum counter stride in floats (256 B) */
#define LOGMIN (-92.10340371976183f)  /* logf(1e-40) */
#define THR   0.05f         /* ALPHA*LAMBD/RHO */
#define SHRK  0.05f         /* (1-ALPHA)*LAMBD */
#define EPSI  1e-10f

__device__ float g_logr0[NROWS * NCOL];
__device__ float g_zbuf[NROWS * NCOL];
__device__ float g_cs[(size_t)NIT * NCOL * CSS];

__global__ void k_zero() {
    g_cs[((size_t)blockIdx.x * NCOL + threadIdx.x) * CSS] = 0.0f;
}

__device__ __forceinline__ float soft(float x) {
    return copysignf(fmaxf(fabsf(x) - THR, 0.0f), x);
}

// Step 0: R_1 = softmax(log R_0c) = R_0c / rowsum(R_0c); Z_0 = 0;
// also writes log(R_0c) scratch and colsum_1 = sum s_td(R_1)^2.
__global__ void __launch_bounds__(NTHR) k_init(const float* __restrict__ r0,
                                               float* __restrict__ R) {
    __shared__ float sp[2][NWARP];
    const int tid  = threadIdx.x;
    const int lane = tid & 31;
    const int wid  = tid >> 5;
    const int col  = tid * 4;
    const size_t rowbase = (size_t)blockIdx.x * G * NCOL + col;

    float c[4] = {0.f, 0.f, 0.f, 0.f};

    float4 rv = *(const float4*)(r0 + rowbase);
    for (int g = 0; g < G; ++g) {
        const size_t base = rowbase + (size_t)g * NCOL;
        float a[4] = {rv.x, rv.y, rv.z, rv.w};
        float lg[4];
#pragma unroll
        for (int j = 0; j < 4; ++j) {
            if (a[j] == 0.0f) { a[j] = 1e-40f; lg[j] = LOGMIN; }
            else              { lg[j] = __logf(a[j]); }
        }
        *(float4*)(g_logr0 + base) = make_float4(lg[0], lg[1], lg[2], lg[3]);

        if (g + 1 < G) rv = *(const float4*)(r0 + base + NCOL);   // prefetch

        float local = (a[0] + a[1]) + (a[2] + a[3]);
#pragma unroll
        for (int o = 16; o > 0; o >>= 1)
            local += __shfl_xor_sync(0xffffffffu, local, o);
        if (lane == 0) sp[g & 1][wid] = local;
        __syncthreads();
        float S = 0.f;
#pragma unroll
        for (int w = 0; w < NWARP; ++w) S += sp[g & 1][w];
        float inv = __fdividef(1.0f, S);

        float rn[4];
#pragma unroll
        for (int j = 0; j < 4; ++j) rn[j] = a[j] * inv;
        *(float4*)(R + base)      = make_float4(rn[0], rn[1], rn[2], rn[3]);
        *(float4*)(g_zbuf + base) = make_float4(0.f, 0.f, 0.f, 0.f);
#pragma unroll
        for (int j = 0; j < 4; ++j) {       // s_td_1 = soft(R_1 + Z_0), Z_0 = 0
            float s = soft(rn[j]);
            c[j] += s * s;
        }
    }
#pragma unroll
    for (int j = 0; j < 4; ++j)
        atomicAdd(&g_cs[((size_t)1 * NCOL + col + j) * CSS], c[j]);
}

// Step k (k=1..19): given (R_k, Z_{k-1}, colsum_k) produce (R_{k+1}, Z_k, colsum_{k+1}).
__global__ void __launch_bounds__(NTHR) k_step(float* __restrict__ R, int k, int last) {
    __shared__ float sp[2][NWARP];
    const int tid  = threadIdx.x;
    const int lane = tid & 31;
    const int wid  = tid >> 5;
    const int col  = tid * 4;
    const size_t rowbase = (size_t)blockIdx.x * G * NCOL + col;

    float sc[4];
#pragma unroll
    for (int j = 0; j < 4; ++j) {
        float cs  = g_cs[((size_t)k * NCOL + col + j) * CSS];
        float nrm = sqrtf(cs);
        sc[j] = fmaxf(1.0f - SHRK / (nrm + EPSI), 0.0f);
    }

    float c[4] = {0.f, 0.f, 0.f, 0.f};
    float4 rv = *(const float4*)(R + rowbase);
    float4 zv = *(const float4*)(g_zbuf + rowbase);
    float4 lv = *(const float4*)(g_logr0 + rowbase);

    for (int g = 0; g < G; ++g) {
        const size_t base = rowbase + (size_t)g * NCOL;
        float r[4] = {rv.x, rv.y, rv.z, rv.w};
        float z[4] = {zv.x, zv.y, zv.z, zv.w};
        float l[4] = {lv.x, lv.y, lv.z, lv.w};

        if (g + 1 < G) {                                   // prefetch next row
            rv = *(const float4*)(R + base + NCOL);
            zv = *(const float4*)(g_zbuf + base + NCOL);
            lv = *(const float4*)(g_logr0 + base + NCOL);
        }

        float e[4], zp[4];
#pragma unroll
        for (int j = 0; j < 4; ++j) {
            float x  = r[j] + z[j];                         // R_k + Z_{k-1}/rho
            float s  = soft(x);
            float X  = sc[j] * s;                           // X_k
            zp[j]    = z[j] + r[j] - X;                     // Z_k
            float lx = (X == 0.0f) ? LOGMIN : __logf(X);
            e[j]     = __expf(0.5f * ((l[j] + lx) - zp[j])); // no max-sub (safe range)
        }

        float local = (e[0] + e[1]) + (e[2] + e[3]);
#pragma unroll
        for (int o = 16; o > 0; o >>= 1)
            local += __shfl_xor_sync(0xffffffffu, local, o);
        if (lane == 0) sp[g & 1][wid] = local;
        __syncthreads();
        float S = 0.f;
#pragma unroll
        for (int w = 0; w < NWARP; ++w) S += sp[g & 1][w];
        float inv = __fdividef(1.0f, S);

        float rn[4];
#pragma unroll
        for (int j = 0; j < 4; ++j) rn[j] = e[j] * inv;     // R_{k+1}
        *(float4*)(R + base) = make_float4(rn[0], rn[1], rn[2], rn[3]);

        if (!last) {
            *(float4*)(g_zbuf + base) = make_float4(zp[0], zp[1], zp[2], zp[3]);
#pragma unroll
            for (int j = 0; j < 4; ++j) {                   // s_td_{k+1}
                float s2 = soft(rn[j] + zp[j]);
                c[j] += s2 * s2;
            }
        }
    }
    if (!last) {
#pragma unroll
        for (int j = 0; j < 4; ++j)
            atomicAdd(&g_cs[((size_t)(k + 1) * NCOL + col + j) * CSS], c[j]);
    }
}

extern "C" void kernel_launch(void* const* d_in, const int* in_sizes, int n_in,
                              void* d_out, int out_size) {
    const float* r0 = (const float*)d_in[0];
    float* out = (float*)d_out;

    k_zero<<<NIT, NCOL>>>();
    k_init<<<NBLK, NTHR>>>(r0, out);
    for (int k = 1; k < NIT; ++k)
        k_step<<<NBLK, NTHR>>>(out, k, (k == NIT - 1) ? 1 : 0);
}